// round 6
// baseline (speedup 1.0000x reference)
#include <cuda_runtime.h>
#include <cuda_fp16.h>
#include <cuda_bf16.h>

// Problem constants
#define B_  8
#define C_  128
#define H_  64
#define W_  64
#define HW_ (H_ * W_)
#define KS  7
#define PAD 3
#define NP  (KS * KS)   // 49 neighborhood offsets

// Scratch for q, k, v in (B, HW, C) channel-contiguous layout
__device__ float g_q[B_ * HW_ * C_];
__device__ float g_k[B_ * HW_ * C_];
__device__ float g_v[B_ * HW_ * C_];

// ---- packed f32x2 helpers (Blackwell sm_100+; PTX-only, ptxas won't emit) ----
__device__ __forceinline__ void fma2(unsigned long long& d,
                                     unsigned long long a,
                                     unsigned long long b) {
    asm("fma.rn.f32x2 %0, %1, %2, %0;" : "+l"(d) : "l"(a), "l"(b));
}
__device__ __forceinline__ unsigned long long splat2(float x) {
    unsigned long long r;
    asm("mov.b64 %0, {%1, %1};" : "=l"(r) : "f"(x));
    return r;
}
__device__ __forceinline__ float2 unpack2(unsigned long long v) {
    float2 r;
    asm("mov.b64 {%0, %1}, %2;" : "=f"(r.x), "=f"(r.y) : "l"(v));
    return r;
}

// ---------------------------------------------------------------------------
// Kernel 1: q/k/v = W @ x + b  (per-batch GEMM: M=128 oc, N=64-px tile, K=128)
// grid = (B*HW/64, 3), block = 256 threads
// thread tile: 4 out-channels x 8 pixels (4 px-PAIRS via fma.rn.f32x2).
// k-chunk = 32 (8 syncs total instead of 16).
// ---------------------------------------------------------------------------
__global__ __launch_bounds__(256) void qkv_gemm(
    const float* __restrict__ x,
    const float* __restrict__ Wq, const float* __restrict__ bq,
    const float* __restrict__ Wk, const float* __restrict__ bk,
    const float* __restrict__ Wv, const float* __restrict__ bv)
{
    __shared__ __align__(16) float Wt[32][132];   // W^T chunk: [k][o], padded
    __shared__ __align__(16) float Xs[32][64];    // x chunk:   [k][p]

    const float* Wm;
    const float* bias;
    float* out;
    if (blockIdx.y == 0)      { Wm = Wq; bias = bq; out = g_q; }
    else if (blockIdx.y == 1) { Wm = Wk; bias = bk; out = g_k; }
    else                      { Wm = Wv; bias = bv; out = g_v; }

    const int t   = blockIdx.x;
    const int b   = t >> 6;           // 64 pixel-tiles per batch image
    const int hw0 = (t & 63) << 6;    // 64 pixels per tile
    const float* xb = x + (size_t)b * C_ * HW_;

    const int og = threadIdx.x & 31;   // out-channel group (fastest)
    const int pg = threadIdx.x >> 5;   // pixel group (one per warp)
    const int o0 = og * 4;
    const int p0 = pg * 8;

    // acc2[i][j] = packed (acc px p0+2j, acc px p0+2j+1), out-channel o0+i
    unsigned long long acc2[4][4];
#pragma unroll
    for (int i = 0; i < 4; ++i)
#pragma unroll
        for (int j = 0; j < 4; ++j) acc2[i][j] = 0ull;

    for (int kk = 0; kk < C_; kk += 32) {
        __syncthreads();
        // load W chunk (4096 floats): cl = i&15 keeps LDG coalesced, STS <=2-way
#pragma unroll
        for (int r = 0; r < 16; ++r) {
            int i   = threadIdx.x + 256 * r;
            int cl  = i & 15;
            int o   = (i >> 4) & 127;
            int khi = i >> 11;                 // 0 or 1
            Wt[cl + 16 * khi][o] = Wm[o * C_ + kk + cl + 16 * khi];
        }
        // load X chunk (2048 floats)
#pragma unroll
        for (int r = 0; r < 8; ++r) {
            int i  = threadIdx.x + 256 * r;
            int pp = i & 63;
            int kl = i >> 6;
            Xs[kl][pp] = xb[(size_t)(kk + kl) * HW_ + hw0 + pp];
        }
        __syncthreads();

#pragma unroll
        for (int k = 0; k < 32; ++k) {
            float4 w4 = *(const float4*)&Wt[k][o0];
            ulonglong2 xp0 = *(const ulonglong2*)&Xs[k][p0];     // px pairs 0,1
            ulonglong2 xp1 = *(const ulonglong2*)&Xs[k][p0 + 4]; // px pairs 2,3
            unsigned long long w2[4] = {splat2(w4.x), splat2(w4.y),
                                        splat2(w4.z), splat2(w4.w)};
            unsigned long long x2[4] = {xp0.x, xp0.y, xp1.x, xp1.y};
#pragma unroll
            for (int i = 0; i < 4; ++i)
#pragma unroll
                for (int j = 0; j < 4; ++j)
                    fma2(acc2[i][j], w2[i], x2[j]);
        }
    }

    // epilogue: add bias, write (B, HW, C) channel-contiguous (coalesced)
    float4 bb = *(const float4*)&bias[o0];
#pragma unroll
    for (int j = 0; j < 4; ++j) {
        float2 a0 = unpack2(acc2[0][j]);
        float2 a1 = unpack2(acc2[1][j]);
        float2 a2 = unpack2(acc2[2][j]);
        float2 a3 = unpack2(acc2[3][j]);
        float4 rlo = make_float4(a0.x + bb.x, a1.x + bb.y, a2.x + bb.z, a3.x + bb.w);
        float4 rhi = make_float4(a0.y + bb.x, a1.y + bb.y, a2.y + bb.z, a3.y + bb.w);
        *(float4*)&out[((size_t)b * HW_ + hw0 + p0 + 2 * j)     * C_ + o0] = rlo;
        *(float4*)&out[((size_t)b * HW_ + hw0 + p0 + 2 * j + 1) * C_ + o0] = rhi;
    }
}

// ---------------------------------------------------------------------------
// Kernel 2: local attention, double-buffered halo staging.
// Tile: 8x8 pixels, 256 threads: 4 threads/pixel (tg = channel quarter, 32 ch).
// Per chunk iteration: issue staging for chunk c+1 into the other buffer,
// compute chunk c, ONE sync. Staging latency hides behind the 49-tap compute.
// ---------------------------------------------------------------------------
#define TW 8
#define TH 8
#define NPX (TW * TH)       // 64 pixels
#define HXW (TW + 6)        // 14
#define HXH (TH + 6)        // 14
#define HPITCH 15           // padded pitch (16B units)
#define HBYTES (HXH * 8 * HPITCH * 16)   // 26880 per buffer

__device__ __forceinline__ void stage_k32(const float* __restrict__ kb,
                                          int c0, int x0, int y0,
                                          float4* __restrict__ hal4, int tid)
{
    for (int i = tid; i < HXH * HXW * 8; i += 256) {
        int j   = i & 7;           // 4-ch sub-group (fastest -> coalesced LDG)
        int pos = i >> 3;
        int hy  = pos / HXW;
        int hx  = pos - hy * HXW;
        int sy  = y0 + hy - PAD, sx = x0 + hx - PAD;
        float4 val = make_float4(0.f, 0.f, 0.f, 0.f);
        if (sy >= 0 && sy < H_ && sx >= 0 && sx < W_)
            val = *(const float4*)&kb[((size_t)sy * W_ + sx) * C_ + c0 + 4 * j];
        hal4[((size_t)hy * 8 + j) * HPITCH + hx] = val;
    }
}

__device__ __forceinline__ void stage_v32(const float* __restrict__ vb,
                                          int c0, int x0, int y0,
                                          uint4* __restrict__ hal2, int tid)
{
    for (int i = tid; i < HXH * HXW * 4; i += 256) {
        int j   = i & 3;           // 8-ch sub-group
        int pos = i >> 2;
        int hy  = pos / HXW;
        int hx  = pos - hy * HXW;
        int sy  = y0 + hy - PAD, sx = x0 + hx - PAD;
        uint4 hv = make_uint4(0u, 0u, 0u, 0u);
        if (sy >= 0 && sy < H_ && sx >= 0 && sx < W_) {
            const float* vp = &vb[((size_t)sy * W_ + sx) * C_ + c0 + 8 * j];
            float4 a = *(const float4*)vp;
            float4 c = *(const float4*)(vp + 4);
            half2 h0 = __floats2half2_rn(a.x, a.y);
            half2 h1 = __floats2half2_rn(a.z, a.w);
            half2 h2 = __floats2half2_rn(c.x, c.y);
            half2 h3 = __floats2half2_rn(c.z, c.w);
            hv.x = *(unsigned*)&h0;
            hv.y = *(unsigned*)&h1;
            hv.z = *(unsigned*)&h2;
            hv.w = *(unsigned*)&h3;
        }
        hal2[((size_t)hy * 4 + j) * HPITCH + hx] = hv;
    }
}

__global__ __launch_bounds__(256, 3) void local_attn(float* __restrict__ out)
{
    __shared__ __align__(16) char s_raw[2 * HBYTES];   // 53.76 KB, double buffer
    float4* buf4[2] = {(float4*)s_raw, (float4*)(s_raw + HBYTES)};
    uint4*  buf2[2] = {(uint4*)s_raw,  (uint4*)(s_raw + HBYTES)};
    float*  rbuf    = (float*)s_raw;    // softmax exchange aliases buffer 0

    const int tid = threadIdx.x;
    const int px = tid & (NPX - 1);
    const int tg = tid >> 6;          // channel quarter: 0..3
    const int tx = px & (TW - 1);
    const int ty = px >> 3;
    const int x0 = blockIdx.x * TW;
    const int y0 = blockIdx.y * TH;
    const int b  = blockIdx.z;
    const int gx = x0 + tx;
    const int gy = y0 + ty;

    const float* qb = g_q + (size_t)b * HW_ * C_;
    const float* kb = g_k + (size_t)b * HW_ * C_;
    const float* vb = g_v + (size_t)b * HW_ * C_;

    float logits[NP];
#pragma unroll
    for (int p = 0; p < NP; ++p) logits[p] = 0.f;

    // ---- Pass 1: partial logits over this thread's 32 channels ----
    stage_k32(kb, 0, x0, y0, buf4[0], tid);
    __syncthreads();
#pragma unroll
    for (int c = 0; c < 4; ++c) {
        if (c < 3) stage_k32(kb, (c + 1) * 32, x0, y0, buf4[(c + 1) & 1], tid);

        const float4* hal4 = buf4[c & 1];
        const float* qp = &qb[((size_t)gy * W_ + gx) * C_ + c * 32 + 8 * tg];
        float4 qf0 = *(const float4*)qp;
        float4 qf1 = *(const float4*)(qp + 4);
#pragma unroll
        for (int p = 0; p < NP; ++p) {
            const int dy = p / KS, dx = p - dy * KS;
            const size_t base = ((size_t)(ty + dy) * 8 + 2 * tg) * HPITCH + (tx + dx);
            float4 k0 = hal4[base];
            float4 k1 = hal4[base + HPITCH];
            float acc = fmaf(qf0.x, k0.x, fmaf(qf0.y, k0.y,
                        fmaf(qf0.z, k0.z, fmaf(qf0.w, k0.w, logits[p]))));
            logits[p] = fmaf(qf1.x, k1.x, fmaf(qf1.y, k1.y,
                        fmaf(qf1.z, k1.z, fmaf(qf1.w, k1.w, acc))));
        }
        __syncthreads();
    }

    // ---- cross-group reduce (4 partials) + softmax (rbuf aliases buffer 0) ----
    float* r0 = rbuf;                 // [64][49]
    float* r1 = rbuf + NPX * NP;      // [64][49]
    if (tg == 2) {
#pragma unroll
        for (int p = 0; p < NP; ++p) r0[px * NP + p] = logits[p];
    } else if (tg == 3) {
#pragma unroll
        for (int p = 0; p < NP; ++p) r1[px * NP + p] = logits[p];
    }
    __syncthreads();
    if (tg == 0) {
#pragma unroll
        for (int p = 0; p < NP; ++p) logits[p] += r0[px * NP + p];
    } else if (tg == 1) {
#pragma unroll
        for (int p = 0; p < NP; ++p) {
            logits[p] += r1[px * NP + p];
            r1[px * NP + p] = logits[p];
        }
    }
    __syncthreads();
    if (tg == 0) {
#pragma unroll
        for (int p = 0; p < NP; ++p) logits[p] += r1[px * NP + p];
        float m = logits[0];
#pragma unroll
        for (int p = 1; p < NP; ++p) m = fmaxf(m, logits[p]);
        float s = 0.f;
#pragma unroll
        for (int p = 0; p < NP; ++p) {
            logits[p] = __expf(logits[p] - m);
            s += logits[p];
        }
        const float inv = 1.f / s;
#pragma unroll
        for (int p = 0; p < NP; ++p) {
            logits[p] *= inv;
            r0[px * NP + p] = logits[p];
        }
    }
    __syncthreads();
    if (tg != 0) {
#pragma unroll
        for (int p = 0; p < NP; ++p) logits[p] = r0[px * NP + p];
    }
    __syncthreads();   // rbuf reads done before pass-2 staging reuses buffer 0

    // ---- Pass 2: y(32 ch) = sum_p attn[p] * v(neighbor); half2-packed halo ----
    stage_v32(vb, 0, x0, y0, buf2[0], tid);
    __syncthreads();
#pragma unroll
    for (int c = 0; c < 4; ++c) {
        if (c < 3) stage_v32(vb, (c + 1) * 32, x0, y0, buf2[(c + 1) & 1], tid);

        const uint4* hal2 = buf2[c & 1];
        float acc8[8];
#pragma unroll
        for (int i = 0; i < 8; ++i) acc8[i] = 0.f;
#pragma unroll
        for (int p = 0; p < NP; ++p) {
            const int dy = p / KS, dx = p - dy * KS;
            uint4 hv = hal2[((size_t)(ty + dy) * 4 + tg) * HPITCH + (tx + dx)];
            const float w = logits[p];
            float2 f0 = __half22float2(*(half2*)&hv.x);
            float2 f1 = __half22float2(*(half2*)&hv.y);
            float2 f2 = __half22float2(*(half2*)&hv.z);
            float2 f3 = __half22float2(*(half2*)&hv.w);
            acc8[0] = fmaf(w, f0.x, acc8[0]);
            acc8[1] = fmaf(w, f0.y, acc8[1]);
            acc8[2] = fmaf(w, f1.x, acc8[2]);
            acc8[3] = fmaf(w, f1.y, acc8[3]);
            acc8[4] = fmaf(w, f2.x, acc8[4]);
            acc8[5] = fmaf(w, f2.y, acc8[5]);
            acc8[6] = fmaf(w, f3.x, acc8[6]);
            acc8[7] = fmaf(w, f3.y, acc8[7]);
        }

        // output in (B, C, H, W); this thread's channels: c*32 + 8*tg .. +7
        const int ch = c * 32 + 8 * tg;
        float* op = out + ((size_t)b * C_ + ch) * HW_ + (size_t)gy * W_ + gx;
#pragma unroll
        for (int i = 0; i < 8; ++i) op[(size_t)i * HW_] = acc8[i];
        __syncthreads();
    }
}

// ---------------------------------------------------------------------------
extern "C" void kernel_launch(void* const* d_in, const int* in_sizes, int n_in,
                              void* d_out, int out_size)
{
    const float* x  = (const float*)d_in[0];
    const float* Wq = (const float*)d_in[1];
    const float* bq = (const float*)d_in[2];
    const float* Wk = (const float*)d_in[3];
    const float* bk = (const float*)d_in[4];
    const float* Wv = (const float*)d_in[5];
    const float* bv = (const float*)d_in[6];
    float* out = (float*)d_out;

    dim3 ggrid(B_ * HW_ / 64, 3, 1);
    qkv_gemm<<<ggrid, 256>>>(x, Wq, bq, Wk, bk, Wv, bv);

    dim3 agrid(W_ / TW, H_ / TH, B_);
    local_attn<<<agrid, 256>>>(out);
}

// round 7
// speedup vs baseline: 1.1280x; 1.1280x over previous
#include <cuda_runtime.h>
#include <cuda_fp16.h>
#include <cuda_bf16.h>

// Problem constants
#define B_  8
#define C_  128
#define H_  64
#define W_  64
#define HW_ (H_ * W_)
#define KS  7
#define PAD 3
#define NP  (KS * KS)   // 49 neighborhood offsets

// Scratch for q, k, v in (B, HW, C) channel-contiguous layout
__device__ float g_q[B_ * HW_ * C_];
__device__ float g_k[B_ * HW_ * C_];
__device__ float g_v[B_ * HW_ * C_];

// ---- packed f32x2 helpers (Blackwell sm_100+; PTX-only, ptxas won't emit) ----
__device__ __forceinline__ void fma2(unsigned long long& d,
                                     unsigned long long a,
                                     unsigned long long b) {
    asm("fma.rn.f32x2 %0, %1, %2, %0;" : "+l"(d) : "l"(a), "l"(b));
}
__device__ __forceinline__ unsigned long long splat2(float x) {
    unsigned long long r;
    asm("mov.b64 %0, {%1, %1};" : "=l"(r) : "f"(x));
    return r;
}
__device__ __forceinline__ float2 unpack2(unsigned long long v) {
    float2 r;
    asm("mov.b64 {%0, %1}, %2;" : "=f"(r.x), "=f"(r.y) : "l"(v));
    return r;
}

// ---------------------------------------------------------------------------
// Kernel 1: q/k/v = W @ x + b  (per-batch GEMM, round-5 version: k-chunk 16)
// grid = (B*HW/64, 3), block = 256 threads
// thread tile: 4 out-channels x 8 pixels (4 px-PAIRS via fma.rn.f32x2).
// ---------------------------------------------------------------------------
__global__ __launch_bounds__(256) void qkv_gemm(
    const float* __restrict__ x,
    const float* __restrict__ Wq, const float* __restrict__ bq,
    const float* __restrict__ Wk, const float* __restrict__ bk,
    const float* __restrict__ Wv, const float* __restrict__ bv)
{
    __shared__ __align__(16) float Wt[16][132];   // W^T chunk: [k][o], padded
    __shared__ __align__(16) float Xs[16][64];    // x chunk:   [k][p]

    const float* Wm;
    const float* bias;
    float* out;
    if (blockIdx.y == 0)      { Wm = Wq; bias = bq; out = g_q; }
    else if (blockIdx.y == 1) { Wm = Wk; bias = bk; out = g_k; }
    else                      { Wm = Wv; bias = bv; out = g_v; }

    const int t   = blockIdx.x;
    const int b   = t >> 6;           // 64 pixel-tiles per batch image
    const int hw0 = (t & 63) << 6;    // 64 pixels per tile
    const float* xb = x + (size_t)b * C_ * HW_;

    const int og = threadIdx.x & 31;   // out-channel group (fastest)
    const int pg = threadIdx.x >> 5;   // pixel group (one per warp)
    const int o0 = og * 4;
    const int p0 = pg * 8;

    unsigned long long acc2[4][4];
#pragma unroll
    for (int i = 0; i < 4; ++i)
#pragma unroll
        for (int j = 0; j < 4; ++j) acc2[i][j] = 0ull;

    for (int kk = 0; kk < C_; kk += 16) {
        __syncthreads();
#pragma unroll
        for (int r = 0; r < 8; ++r) {
            int i  = threadIdx.x + 256 * r;
            int cl = i & 15;
            int o  = i >> 4;
            Wt[cl][o] = Wm[o * C_ + kk + cl];
        }
#pragma unroll
        for (int r = 0; r < 4; ++r) {
            int i  = threadIdx.x + 256 * r;
            int pp = i & 63;
            int kl = i >> 6;
            Xs[kl][pp] = xb[(size_t)(kk + kl) * HW_ + hw0 + pp];
        }
        __syncthreads();

#pragma unroll
        for (int k = 0; k < 16; ++k) {
            float4 w4 = *(const float4*)&Wt[k][o0];
            ulonglong2 xp0 = *(const ulonglong2*)&Xs[k][p0];
            ulonglong2 xp1 = *(const ulonglong2*)&Xs[k][p0 + 4];
            unsigned long long w2[4] = {splat2(w4.x), splat2(w4.y),
                                        splat2(w4.z), splat2(w4.w)};
            unsigned long long x2[4] = {xp0.x, xp0.y, xp1.x, xp1.y};
#pragma unroll
            for (int i = 0; i < 4; ++i)
#pragma unroll
                for (int j = 0; j < 4; ++j)
                    fma2(acc2[i][j], w2[i], x2[j]);
        }
    }

    float4 bb = *(const float4*)&bias[o0];
#pragma unroll
    for (int j = 0; j < 4; ++j) {
        float2 a0 = unpack2(acc2[0][j]);
        float2 a1 = unpack2(acc2[1][j]);
        float2 a2 = unpack2(acc2[2][j]);
        float2 a3 = unpack2(acc2[3][j]);
        float4 rlo = make_float4(a0.x + bb.x, a1.x + bb.y, a2.x + bb.z, a3.x + bb.w);
        float4 rhi = make_float4(a0.y + bb.x, a1.y + bb.y, a2.y + bb.z, a3.y + bb.w);
        *(float4*)&out[((size_t)b * HW_ + hw0 + p0 + 2 * j)     * C_ + o0] = rlo;
        *(float4*)&out[((size_t)b * HW_ + hw0 + p0 + 2 * j + 1) * C_ + o0] = rhi;
    }
}

// ---------------------------------------------------------------------------
// Kernel 2: local attention, shuffle-softmax version.
// Tile 8x8 px, 256 threads. Warp = pixel row (ty); lane = tg*8 + tx, so the
// 4 channel-quarter partials of a pixel sit in ONE warp -> logit reduction is
// two shfl_xor ops (no smem exchange, no extra syncs). Softmax is computed
// redundantly in every lane.
// Single-buffer halo staging (round-5 structure; double-buffer regressed).
// ---------------------------------------------------------------------------
#define TW 8
#define TH 8
#define HXW (TW + 6)        // 14
#define HXH (TH + 6)        // 14
#define HPITCH 15           // padded pitch (16B units)

__global__ __launch_bounds__(256, 3) void local_attn(float* __restrict__ out)
{
    __shared__ __align__(16) char s_raw[HXH * 8 * HPITCH * 16];  // 26.25 KB
    float4* hal4 = (float4*)s_raw;   // [hy][j(0..7)][hx] fp32, 4 ch per float4
    uint4*  hal2 = (uint4*)s_raw;    // [hy][j(0..3)][hx] half2, 8 ch per uint4

    const int tid  = threadIdx.x;
    const int ty   = tid >> 5;            // warp = pixel row
    const int lane = tid & 31;
    const int tg   = lane >> 3;           // channel quarter 0..3
    const int tx   = lane & 7;            // pixel column
    const int x0 = blockIdx.x * TW;
    const int y0 = blockIdx.y * TH;
    const int b  = blockIdx.z;
    const int gx = x0 + tx;
    const int gy = y0 + ty;

    const float* qb = g_q + (size_t)b * HW_ * C_;
    const float* kb = g_k + (size_t)b * HW_ * C_;
    const float* vb = g_v + (size_t)b * HW_ * C_;

    float logits[NP];
#pragma unroll
    for (int p = 0; p < NP; ++p) logits[p] = 0.f;

    // ---- Pass 1: partial logits over this thread's 32 channels (fp32 halo) ----
    for (int c0 = 0; c0 < C_; c0 += 32) {
        __syncthreads();
        for (int i = tid; i < HXH * HXW * 8; i += 256) {
            int j   = i & 7;
            int pos = i >> 3;
            int hy  = pos / HXW;
            int hx  = pos - hy * HXW;
            int sy  = y0 + hy - PAD, sx = x0 + hx - PAD;
            float4 val = make_float4(0.f, 0.f, 0.f, 0.f);
            if (sy >= 0 && sy < H_ && sx >= 0 && sx < W_)
                val = *(const float4*)&kb[((size_t)sy * W_ + sx) * C_ + c0 + 4 * j];
            hal4[((size_t)hy * 8 + j) * HPITCH + hx] = val;
        }
        __syncthreads();

        const float* qp = &qb[((size_t)gy * W_ + gx) * C_ + c0 + 8 * tg];
        float4 qf0 = *(const float4*)qp;
        float4 qf1 = *(const float4*)(qp + 4);
#pragma unroll
        for (int p = 0; p < NP; ++p) {
            const int dy = p / KS, dx = p - dy * KS;
            const size_t base = ((size_t)(ty + dy) * 8 + 2 * tg) * HPITCH + (tx + dx);
            float4 k0 = hal4[base];
            float4 k1 = hal4[base + HPITCH];
            float acc = fmaf(qf0.x, k0.x, fmaf(qf0.y, k0.y,
                        fmaf(qf0.z, k0.z, fmaf(qf0.w, k0.w, logits[p]))));
            logits[p] = fmaf(qf1.x, k1.x, fmaf(qf1.y, k1.y,
                        fmaf(qf1.z, k1.z, fmaf(qf1.w, k1.w, acc))));
        }
    }

    // ---- cross-quarter reduce via warp shuffles + redundant softmax ----
#pragma unroll
    for (int p = 0; p < NP; ++p) {
        logits[p] += __shfl_xor_sync(0xffffffffu, logits[p], 8);
        logits[p] += __shfl_xor_sync(0xffffffffu, logits[p], 16);
    }
    {
        float m = logits[0];
#pragma unroll
        for (int p = 1; p < NP; ++p) m = fmaxf(m, logits[p]);
        float s = 0.f;
#pragma unroll
        for (int p = 0; p < NP; ++p) {
            logits[p] = __expf(logits[p] - m);
            s += logits[p];
        }
        const float inv = 1.f / s;
#pragma unroll
        for (int p = 0; p < NP; ++p) logits[p] *= inv;
    }

    // ---- Pass 2: y(32 ch) = sum_p attn[p] * v(neighbor); half2-packed halo ----
    for (int c0 = 0; c0 < C_; c0 += 32) {
        __syncthreads();
        for (int i = tid; i < HXH * HXW * 4; i += 256) {
            int j   = i & 3;
            int pos = i >> 2;
            int hy  = pos / HXW;
            int hx  = pos - hy * HXW;
            int sy  = y0 + hy - PAD, sx = x0 + hx - PAD;
            uint4 hv = make_uint4(0u, 0u, 0u, 0u);
            if (sy >= 0 && sy < H_ && sx >= 0 && sx < W_) {
                const float* vp = &vb[((size_t)sy * W_ + sx) * C_ + c0 + 8 * j];
                float4 a = *(const float4*)vp;
                float4 c = *(const float4*)(vp + 4);
                half2 h0 = __floats2half2_rn(a.x, a.y);
                half2 h1 = __floats2half2_rn(a.z, a.w);
                half2 h2 = __floats2half2_rn(c.x, c.y);
                half2 h3 = __floats2half2_rn(c.z, c.w);
                hv.x = *(unsigned*)&h0;
                hv.y = *(unsigned*)&h1;
                hv.z = *(unsigned*)&h2;
                hv.w = *(unsigned*)&h3;
            }
            hal2[((size_t)hy * 4 + j) * HPITCH + hx] = hv;
        }
        __syncthreads();

        float acc8[8];
#pragma unroll
        for (int i = 0; i < 8; ++i) acc8[i] = 0.f;
#pragma unroll
        for (int p = 0; p < NP; ++p) {
            const int dy = p / KS, dx = p - dy * KS;
            uint4 hv = hal2[((size_t)(ty + dy) * 4 + tg) * HPITCH + (tx + dx)];
            const float w = logits[p];
            float2 f0 = __half22float2(*(half2*)&hv.x);
            float2 f1 = __half22float2(*(half2*)&hv.y);
            float2 f2 = __half22float2(*(half2*)&hv.z);
            float2 f3 = __half22float2(*(half2*)&hv.w);
            acc8[0] = fmaf(w, f0.x, acc8[0]);
            acc8[1] = fmaf(w, f0.y, acc8[1]);
            acc8[2] = fmaf(w, f1.x, acc8[2]);
            acc8[3] = fmaf(w, f1.y, acc8[3]);
            acc8[4] = fmaf(w, f2.x, acc8[4]);
            acc8[5] = fmaf(w, f2.y, acc8[5]);
            acc8[6] = fmaf(w, f3.x, acc8[6]);
            acc8[7] = fmaf(w, f3.y, acc8[7]);
        }

        const int ch = c0 + 8 * tg;
        float* op = out + ((size_t)b * C_ + ch) * HW_ + (size_t)gy * W_ + gx;
#pragma unroll
        for (int i = 0; i < 8; ++i) op[(size_t)i * HW_] = acc8[i];
    }
}

// ---------------------------------------------------------------------------
extern "C" void kernel_launch(void* const* d_in, const int* in_sizes, int n_in,
                              void* d_out, int out_size)
{
    const float* x  = (const float*)d_in[0];
    const float* Wq = (const float*)d_in[1];
    const float* bq = (const float*)d_in[2];
    const float* Wk = (const float*)d_in[3];
    const float* bk = (const float*)d_in[4];
    const float* Wv = (const float*)d_in[5];
    const float* bv = (const float*)d_in[6];
    float* out = (float*)d_out;

    dim3 ggrid(B_ * HW_ / 64, 3, 1);
    qkv_gemm<<<ggrid, 256>>>(x, Wq, bq, Wk, bk, Wv, bv);

    dim3 agrid(W_ / TW, H_ / TH, B_);
    local_attn<<<agrid, 256>>>(out);
}